// round 1
// baseline (speedup 1.0000x reference)
#include <cuda_runtime.h>
#include <cstdint>

// ---------------------------------------------------------------------------
// MoE forward: T=8192 tokens, D=768, F=3072, E=8, top-2, capacity=2560
// Sparse dispatch: per-(k,e) ordered scan -> compacted per-expert token lists,
// then two gathered fp32 GEMMs per expert (gate/up fused, silu fused, combine
// weight folded into h). fp32 baseline round.
// ---------------------------------------------------------------------------

#define T_TOK   8192
#define D_DIM   768
#define F_DIM   3072
#define E_NUM   8
#define K_TOP   2
#define CAP     2560
#define MAXROWS (T_TOK * K_TOP)   // 16384 max kept token-expert pairs

// ---- device scratch (module-scope allocations; allowed) -------------------
__device__ int   g_topk_idx[T_TOK * 2];
__device__ float g_topk_w  [T_TOK * 2];
__device__ int   g_tok [MAXROWS];
__device__ float g_wt  [MAXROWS];
__device__ int   g_cnt [E_NUM];
__device__ int   g_base[E_NUM];
__device__ float g_P   [E_NUM];
__device__ float g_f   [E_NUM];
__device__ float g_z;
__device__ float g_h[(size_t)MAXROWS * F_DIM];   // ~201 MB hidden scratch

// ---------------------------------------------------------------------------
__global__ void init_kernel() {
    int t = threadIdx.x;
    if (t < E_NUM) { g_P[t] = 0.f; g_f[t] = 0.f; }
    if (t == 0) g_z = 0.f;
}

// ---------------------------------------------------------------------------
// Router: one warp per token. Computes logits[8], softmax, top-2 (tie-break
// lowest index like jax top_k), normalized top-2 weights, and accumulates
// P (mean probs), f (assignment counts), z (sum of lse^2).
// ---------------------------------------------------------------------------
__global__ __launch_bounds__(128) void router_kernel(
    const float* __restrict__ x, const float* __restrict__ w_gate)
{
    int warp = threadIdx.x >> 5;
    int lane = threadIdx.x & 31;
    int t = blockIdx.x * 4 + warp;
    if (t >= T_TOK) return;

    const float* xr = x + (size_t)t * D_DIM;
    float a[24];
#pragma unroll
    for (int i = 0; i < 24; i++) a[i] = xr[i * 32 + lane];

    float logits[E_NUM];
#pragma unroll
    for (int e = 0; e < E_NUM; e++) {
        const float* w = w_gate + (size_t)e * D_DIM;
        float s = 0.f;
#pragma unroll
        for (int i = 0; i < 24; i++) s += a[i] * w[i * 32 + lane];
#pragma unroll
        for (int o = 16; o; o >>= 1) s += __shfl_xor_sync(0xffffffffu, s, o);
        logits[e] = s;
    }

    if (lane == 0) {
        float mx = logits[0];
#pragma unroll
        for (int e = 1; e < E_NUM; e++) mx = fmaxf(mx, logits[e]);
        float pe[E_NUM], se = 0.f;
#pragma unroll
        for (int e = 0; e < E_NUM; e++) { pe[e] = expf(logits[e] - mx); se += pe[e]; }
        float inv = 1.f / se;

        int i0 = 0; float p0 = pe[0];
#pragma unroll
        for (int e = 1; e < E_NUM; e++) if (pe[e] > p0) { p0 = pe[e]; i0 = e; }
        int i1 = -1; float p1 = -1.f;
#pragma unroll
        for (int e = 0; e < E_NUM; e++) if (e != i0 && pe[e] > p1) { p1 = pe[e]; i1 = e; }

        float q0 = p0 * inv, q1 = p1 * inv;
        float sn = 1.f / (q0 + q1);
        g_topk_idx[t * 2 + 0] = i0;
        g_topk_idx[t * 2 + 1] = i1;
        g_topk_w  [t * 2 + 0] = q0 * sn;
        g_topk_w  [t * 2 + 1] = q1 * sn;

        float lse = mx + logf(se);
        atomicAdd(&g_z, lse * lse);
#pragma unroll
        for (int e = 0; e < E_NUM; e++) atomicAdd(&g_P[e], pe[e] * inv);
        atomicAdd(&g_f[i0], 1.f);
        atomicAdd(&g_f[i1], 1.f);
    }
}

// ---------------------------------------------------------------------------
// Scan/dispatch: 1 block, 16 warps; warp w handles (k = w>>3, e = w&7).
// Pass 0 counts totals per (k,e); thread 0 builds capacity-truncated counts,
// k=1 offsets, and per-expert base prefix; pass 1 writes compacted lists in
// token order (rank == compacted position among kept).
// ---------------------------------------------------------------------------
__global__ __launch_bounds__(512) void scan_kernel()
{
    __shared__ int tot[2][E_NUM];
    __shared__ int off1[E_NUM];
    __shared__ int baseS[E_NUM];

    int tid = threadIdx.x, w = tid >> 5, lane = tid & 31;
    int k = w >> 3, e = w & 7;

    int run = 0;
    for (int c = 0; c < T_TOK / 32; c++) {
        int t = c * 32 + lane;
        int f = (g_topk_idx[t * 2 + k] == e);
        run += __popc(__ballot_sync(0xffffffffu, f));
    }
    if (lane == 0) tot[k][e] = run;
    __syncthreads();

    if (tid == 0) {
        int b = 0;
        for (int ee = 0; ee < E_NUM; ee++) {
            int k0 = min(tot[0][ee], CAP);
            int k1 = min(tot[1][ee], CAP);
            off1[ee] = k0;
            int c = k0 + k1;
            g_cnt[ee] = c;
            baseS[ee] = b;
            g_base[ee] = b;
            b += c;
        }
    }
    __syncthreads();

    int pos0 = baseS[e] + (k == 0 ? 0 : off1[e]);
    run = 0;
    for (int c = 0; c < T_TOK / 32; c++) {
        int t = c * 32 + lane;
        bool f = (g_topk_idx[t * 2 + k] == e);
        unsigned bal = __ballot_sync(0xffffffffu, f);
        int rank = run + __popc(bal & ((1u << lane) - 1u));
        if (f && rank < CAP) {
            g_tok[pos0 + rank] = t;
            g_wt [pos0 + rank] = g_topk_w[t * 2 + k];
        }
        run += __popc(bal);
    }
}

// ---------------------------------------------------------------------------
// Tiled fp32 GEMMs. Tile 64x64, BK=16, 256 threads, 4x4 microtile.
// Both operands K-contiguous (NT). Smem stored k-major with stride BM+4=68
// (272B rows: 16B aligned for float4, 2-way-max bank conflicts).
// ---------------------------------------------------------------------------
#define BM 64
#define BN 64
#define BK 16
#define LDS_ (BM + 4)

__device__ __forceinline__ float silu_f(float g) {
    return g / (1.f + __expf(-g));
}

__global__ __launch_bounds__(256) void ffn1_kernel(
    const float* __restrict__ x,
    const float* __restrict__ wig,
    const float* __restrict__ wiu)
{
    int e   = blockIdx.z;
    int cnt = g_cnt[e];
    int m0  = blockIdx.x * BM;
    if (m0 >= cnt) return;
    int n0   = blockIdx.y * BN;
    int base = g_base[e];

    __shared__ __align__(16) float As[BK][LDS_];
    __shared__ __align__(16) float Bg[BK][LDS_];
    __shared__ __align__(16) float Bu[BK][LDS_];
    __shared__ int   toks[BM];
    __shared__ float wts [BM];

    int tid = threadIdx.x;
    if (tid < BM) {
        int m = m0 + tid;
        toks[tid] = (m < cnt) ? g_tok[base + m] : 0;
        wts [tid] = (m < cnt) ? g_wt [base + m] : 0.f;
    }
    __syncthreads();

    const float* wg_ = wig + (size_t)e * F_DIM * D_DIM;
    const float* wu_ = wiu + (size_t)e * F_DIM * D_DIM;

    int lm = tid >> 2;          // 0..63 : tile row
    int lk = (tid & 3) * 4;     // 0,4,8,12 : k offset (float4)
    int tx = tid & 15, ty = tid >> 4;

    float accg[4][4] = {{0.f}}, accu[4][4] = {{0.f}};

    int  tokm  = toks[lm];
    bool valid = (m0 + lm) < cnt;
    const float* arow = x   + (size_t)tokm * D_DIM;
    const float* grow = wg_ + (size_t)(n0 + lm) * D_DIM;
    const float* urow = wu_ + (size_t)(n0 + lm) * D_DIM;

    for (int k0 = 0; k0 < D_DIM; k0 += BK) {
        float4 av = valid ? *(const float4*)(arow + k0 + lk)
                          : make_float4(0.f, 0.f, 0.f, 0.f);
        float4 gv = *(const float4*)(grow + k0 + lk);
        float4 uv = *(const float4*)(urow + k0 + lk);
        __syncthreads();
        As[lk + 0][lm] = av.x; As[lk + 1][lm] = av.y;
        As[lk + 2][lm] = av.z; As[lk + 3][lm] = av.w;
        Bg[lk + 0][lm] = gv.x; Bg[lk + 1][lm] = gv.y;
        Bg[lk + 2][lm] = gv.z; Bg[lk + 3][lm] = gv.w;
        Bu[lk + 0][lm] = uv.x; Bu[lk + 1][lm] = uv.y;
        Bu[lk + 2][lm] = uv.z; Bu[lk + 3][lm] = uv.w;
        __syncthreads();
#pragma unroll
        for (int kk = 0; kk < BK; kk++) {
            float a[4];
            a[0] = As[kk][ty * 4 + 0]; a[1] = As[kk][ty * 4 + 1];
            a[2] = As[kk][ty * 4 + 2]; a[3] = As[kk][ty * 4 + 3];
            float4 bg4 = *(const float4*)&Bg[kk][tx * 4];
            float4 bu4 = *(const float4*)&Bu[kk][tx * 4];
            float bg[4] = {bg4.x, bg4.y, bg4.z, bg4.w};
            float bu[4] = {bu4.x, bu4.y, bu4.z, bu4.w};
#pragma unroll
            for (int i = 0; i < 4; i++)
#pragma unroll
                for (int j = 0; j < 4; j++) {
                    accg[i][j] += a[i] * bg[j];
                    accu[i][j] += a[i] * bu[j];
                }
        }
    }

#pragma unroll
    for (int i = 0; i < 4; i++) {
        int m = m0 + ty * 4 + i;
        if (m < cnt) {
            float wt = wts[ty * 4 + i];
            float4 hv;
            hv.x = silu_f(accg[i][0]) * accu[i][0] * wt;
            hv.y = silu_f(accg[i][1]) * accu[i][1] * wt;
            hv.z = silu_f(accg[i][2]) * accu[i][2] * wt;
            hv.w = silu_f(accg[i][3]) * accu[i][3] * wt;
            *(float4*)&g_h[(size_t)(base + m) * F_DIM + n0 + tx * 4] = hv;
        }
    }
}

__global__ __launch_bounds__(256) void ffn2_kernel(
    const float* __restrict__ wo, float* __restrict__ out)
{
    int e   = blockIdx.z;
    int cnt = g_cnt[e];
    int m0  = blockIdx.x * BM;
    if (m0 >= cnt) return;
    int n0   = blockIdx.y * BN;
    int base = g_base[e];

    __shared__ __align__(16) float As[BK][LDS_];
    __shared__ __align__(16) float Bs[BK][LDS_];
    __shared__ int toks[BM];

    int tid = threadIdx.x;
    if (tid < BM) {
        int m = m0 + tid;
        toks[tid] = (m < cnt) ? g_tok[base + m] : 0;
    }
    __syncthreads();

    const float* wo_ = wo + (size_t)e * D_DIM * F_DIM;

    int lm = tid >> 2;
    int lk = (tid & 3) * 4;
    int tx = tid & 15, ty = tid >> 4;

    float acc[4][4] = {{0.f}};

    bool valid = (m0 + lm) < cnt;
    const float* arow = g_h + (size_t)(base + m0 + lm) * F_DIM;
    const float* brow = wo_ + (size_t)(n0 + lm) * F_DIM;

    for (int k0 = 0; k0 < F_DIM; k0 += BK) {
        float4 av = valid ? *(const float4*)(arow + k0 + lk)
                          : make_float4(0.f, 0.f, 0.f, 0.f);
        float4 bv = *(const float4*)(brow + k0 + lk);
        __syncthreads();
        As[lk + 0][lm] = av.x; As[lk + 1][lm] = av.y;
        As[lk + 2][lm] = av.z; As[lk + 3][lm] = av.w;
        Bs[lk + 0][lm] = bv.x; Bs[lk + 1][lm] = bv.y;
        Bs[lk + 2][lm] = bv.z; Bs[lk + 3][lm] = bv.w;
        __syncthreads();
#pragma unroll
        for (int kk = 0; kk < BK; kk++) {
            float a[4];
            a[0] = As[kk][ty * 4 + 0]; a[1] = As[kk][ty * 4 + 1];
            a[2] = As[kk][ty * 4 + 2]; a[3] = As[kk][ty * 4 + 3];
            float4 b4 = *(const float4*)&Bs[kk][tx * 4];
            float b[4] = {b4.x, b4.y, b4.z, b4.w};
#pragma unroll
            for (int i = 0; i < 4; i++)
#pragma unroll
                for (int j = 0; j < 4; j++)
                    acc[i][j] += a[i] * b[j];
        }
    }

#pragma unroll
    for (int i = 0; i < 4; i++) {
        int mi = ty * 4 + i;
        int m = m0 + mi;
        if (m < cnt) {
            int tok = toks[mi];
            float* orow = out + (size_t)tok * D_DIM + n0 + tx * 4;
#pragma unroll
            for (int j = 0; j < 4; j++)
                atomicAdd(orow + j, acc[i][j]);
        }
    }
}

// ---------------------------------------------------------------------------
__global__ void aux_kernel(float* __restrict__ out, int out_size)
{
    if (threadIdx.x == 0) {
        float lb = 0.f;
        for (int e = 0; e < E_NUM; e++)
            lb += (g_f[e] / (float)(T_TOK * K_TOP)) * (g_P[e] / (float)T_TOK);
        float aux = 0.01f * (float)E_NUM * lb + 0.001f * (g_z / (float)T_TOK);
        if (out_size > T_TOK * D_DIM)
            out[T_TOK * D_DIM] = aux;
    }
}

// ---------------------------------------------------------------------------
extern "C" void kernel_launch(void* const* d_in, const int* in_sizes, int n_in,
                              void* d_out, int out_size)
{
    const float* x       = (const float*)d_in[0];
    const float* w_gate  = (const float*)d_in[1];
    const float* wi_gate = (const float*)d_in[2];
    const float* wi_up   = (const float*)d_in[3];
    const float* wo      = (const float*)d_in[4];
    float* out = (float*)d_out;

    cudaMemsetAsync(d_out, 0, (size_t)out_size * sizeof(float));
    init_kernel<<<1, 32>>>();
    router_kernel<<<T_TOK / 4, 128>>>(x, w_gate);
    scan_kernel<<<1, 512>>>();
    ffn1_kernel<<<dim3(CAP * 2 / BM, F_DIM / BN, E_NUM), 256>>>(x, wi_gate, wi_up);
    ffn2_kernel<<<dim3(CAP * 2 / BM, D_DIM / BN, E_NUM), 256>>>(wo, out);
    aux_kernel<<<1, 32>>>(out, out_size);
}

// round 2
// speedup vs baseline: 1.0009x; 1.0009x over previous
#include <cuda_runtime.h>
#include <cstdint>

// ---------------------------------------------------------------------------
// MoE forward: T=8192 tokens, D=768, F=3072, E=8, top-2, capacity=2560
// Sparse dispatch: per-(k,e) ordered scan -> compacted per-expert token lists,
// then two gathered fp32 GEMMs per expert (gate/up fused, silu fused, combine
// weight folded into h). fp32 baseline round.
// ---------------------------------------------------------------------------

#define T_TOK   8192
#define D_DIM   768
#define F_DIM   3072
#define E_NUM   8
#define K_TOP   2
#define CAP     2560
#define MAXROWS (T_TOK * K_TOP)   // 16384 max kept token-expert pairs

// ---- device scratch (module-scope allocations; allowed) -------------------
__device__ int   g_topk_idx[T_TOK * 2];
__device__ float g_topk_w  [T_TOK * 2];
__device__ int   g_tok [MAXROWS];
__device__ float g_wt  [MAXROWS];
__device__ int   g_cnt [E_NUM];
__device__ int   g_base[E_NUM];
__device__ float g_P   [E_NUM];
__device__ float g_f   [E_NUM];
__device__ float g_z;
__device__ float g_h[(size_t)MAXROWS * F_DIM];   // ~201 MB hidden scratch

// ---------------------------------------------------------------------------
__global__ void init_kernel() {
    int t = threadIdx.x;
    if (t < E_NUM) { g_P[t] = 0.f; g_f[t] = 0.f; }
    if (t == 0) g_z = 0.f;
}

// ---------------------------------------------------------------------------
// Router: one warp per token. Computes logits[8], softmax, top-2 (tie-break
// lowest index like jax top_k), normalized top-2 weights, and accumulates
// P (mean probs), f (assignment counts), z (sum of lse^2).
// ---------------------------------------------------------------------------
__global__ __launch_bounds__(128) void router_kernel(
    const float* __restrict__ x, const float* __restrict__ w_gate)
{
    int warp = threadIdx.x >> 5;
    int lane = threadIdx.x & 31;
    int t = blockIdx.x * 4 + warp;
    if (t >= T_TOK) return;

    const float* xr = x + (size_t)t * D_DIM;
    float a[24];
#pragma unroll
    for (int i = 0; i < 24; i++) a[i] = xr[i * 32 + lane];

    float logits[E_NUM];
#pragma unroll
    for (int e = 0; e < E_NUM; e++) {
        const float* w = w_gate + (size_t)e * D_DIM;
        float s = 0.f;
#pragma unroll
        for (int i = 0; i < 24; i++) s += a[i] * w[i * 32 + lane];
#pragma unroll
        for (int o = 16; o; o >>= 1) s += __shfl_xor_sync(0xffffffffu, s, o);
        logits[e] = s;
    }

    if (lane == 0) {
        float mx = logits[0];
#pragma unroll
        for (int e = 1; e < E_NUM; e++) mx = fmaxf(mx, logits[e]);
        float pe[E_NUM], se = 0.f;
#pragma unroll
        for (int e = 0; e < E_NUM; e++) { pe[e] = expf(logits[e] - mx); se += pe[e]; }
        float inv = 1.f / se;

        int i0 = 0; float p0 = pe[0];
#pragma unroll
        for (int e = 1; e < E_NUM; e++) if (pe[e] > p0) { p0 = pe[e]; i0 = e; }
        int i1 = -1; float p1 = -1.f;
#pragma unroll
        for (int e = 0; e < E_NUM; e++) if (e != i0 && pe[e] > p1) { p1 = pe[e]; i1 = e; }

        float q0 = p0 * inv, q1 = p1 * inv;
        float sn = 1.f / (q0 + q1);
        g_topk_idx[t * 2 + 0] = i0;
        g_topk_idx[t * 2 + 1] = i1;
        g_topk_w  [t * 2 + 0] = q0 * sn;
        g_topk_w  [t * 2 + 1] = q1 * sn;

        float lse = mx + logf(se);
        atomicAdd(&g_z, lse * lse);
#pragma unroll
        for (int e = 0; e < E_NUM; e++) atomicAdd(&g_P[e], pe[e] * inv);
        atomicAdd(&g_f[i0], 1.f);
        atomicAdd(&g_f[i1], 1.f);
    }
}

// ---------------------------------------------------------------------------
// Scan/dispatch: 1 block, 16 warps; warp w handles (k = w>>3, e = w&7).
// Pass 0 counts totals per (k,e); thread 0 builds capacity-truncated counts,
// k=1 offsets, and per-expert base prefix; pass 1 writes compacted lists in
// token order (rank == compacted position among kept).
// ---------------------------------------------------------------------------
__global__ __launch_bounds__(512) void scan_kernel()
{
    __shared__ int tot[2][E_NUM];
    __shared__ int off1[E_NUM];
    __shared__ int baseS[E_NUM];

    int tid = threadIdx.x, w = tid >> 5, lane = tid & 31;
    int k = w >> 3, e = w & 7;

    int run = 0;
    for (int c = 0; c < T_TOK / 32; c++) {
        int t = c * 32 + lane;
        int f = (g_topk_idx[t * 2 + k] == e);
        run += __popc(__ballot_sync(0xffffffffu, f));
    }
    if (lane == 0) tot[k][e] = run;
    __syncthreads();

    if (tid == 0) {
        int b = 0;
        for (int ee = 0; ee < E_NUM; ee++) {
            int k0 = min(tot[0][ee], CAP);
            int k1 = min(tot[1][ee], CAP);
            off1[ee] = k0;
            int c = k0 + k1;
            g_cnt[ee] = c;
            baseS[ee] = b;
            g_base[ee] = b;
            b += c;
        }
    }
    __syncthreads();

    int pos0 = baseS[e] + (k == 0 ? 0 : off1[e]);
    run = 0;
    for (int c = 0; c < T_TOK / 32; c++) {
        int t = c * 32 + lane;
        bool f = (g_topk_idx[t * 2 + k] == e);
        unsigned bal = __ballot_sync(0xffffffffu, f);
        int rank = run + __popc(bal & ((1u << lane) - 1u));
        if (f && rank < CAP) {
            g_tok[pos0 + rank] = t;
            g_wt [pos0 + rank] = g_topk_w[t * 2 + k];
        }
        run += __popc(bal);
    }
}

// ---------------------------------------------------------------------------
// Tiled fp32 GEMMs. Tile 64x64, BK=16, 256 threads, 4x4 microtile.
// Both operands K-contiguous (NT). Smem stored k-major with stride BM+4=68
// (272B rows: 16B aligned for float4, 2-way-max bank conflicts).
// ---------------------------------------------------------------------------
#define BM 64
#define BN 64
#define BK 16
#define LDS_ (BM + 4)

__device__ __forceinline__ float silu_f(float g) {
    return g / (1.f + __expf(-g));
}

__global__ __launch_bounds__(256) void ffn1_kernel(
    const float* __restrict__ x,
    const float* __restrict__ wig,
    const float* __restrict__ wiu)
{
    int e   = blockIdx.z;
    int cnt = g_cnt[e];
    int m0  = blockIdx.x * BM;
    if (m0 >= cnt) return;
    int n0   = blockIdx.y * BN;
    int base = g_base[e];

    __shared__ __align__(16) float As[BK][LDS_];
    __shared__ __align__(16) float Bg[BK][LDS_];
    __shared__ __align__(16) float Bu[BK][LDS_];
    __shared__ int   toks[BM];
    __shared__ float wts [BM];

    int tid = threadIdx.x;
    if (tid < BM) {
        int m = m0 + tid;
        toks[tid] = (m < cnt) ? g_tok[base + m] : 0;
        wts [tid] = (m < cnt) ? g_wt [base + m] : 0.f;
    }
    __syncthreads();

    const float* wg_ = wig + (size_t)e * F_DIM * D_DIM;
    const float* wu_ = wiu + (size_t)e * F_DIM * D_DIM;

    int lm = tid >> 2;          // 0..63 : tile row
    int lk = (tid & 3) * 4;     // 0,4,8,12 : k offset (float4)
    int tx = tid & 15, ty = tid >> 4;

    float accg[4][4] = {{0.f}}, accu[4][4] = {{0.f}};

    int  tokm  = toks[lm];
    bool valid = (m0 + lm) < cnt;
    const float* arow = x   + (size_t)tokm * D_DIM;
    const float* grow = wg_ + (size_t)(n0 + lm) * D_DIM;
    const float* urow = wu_ + (size_t)(n0 + lm) * D_DIM;

    for (int k0 = 0; k0 < D_DIM; k0 += BK) {
        float4 av = valid ? *(const float4*)(arow + k0 + lk)
                          : make_float4(0.f, 0.f, 0.f, 0.f);
        float4 gv = *(const float4*)(grow + k0 + lk);
        float4 uv = *(const float4*)(urow + k0 + lk);
        __syncthreads();
        As[lk + 0][lm] = av.x; As[lk + 1][lm] = av.y;
        As[lk + 2][lm] = av.z; As[lk + 3][lm] = av.w;
        Bg[lk + 0][lm] = gv.x; Bg[lk + 1][lm] = gv.y;
        Bg[lk + 2][lm] = gv.z; Bg[lk + 3][lm] = gv.w;
        Bu[lk + 0][lm] = uv.x; Bu[lk + 1][lm] = uv.y;
        Bu[lk + 2][lm] = uv.z; Bu[lk + 3][lm] = uv.w;
        __syncthreads();
#pragma unroll
        for (int kk = 0; kk < BK; kk++) {
            float a[4];
            a[0] = As[kk][ty * 4 + 0]; a[1] = As[kk][ty * 4 + 1];
            a[2] = As[kk][ty * 4 + 2]; a[3] = As[kk][ty * 4 + 3];
            float4 bg4 = *(const float4*)&Bg[kk][tx * 4];
            float4 bu4 = *(const float4*)&Bu[kk][tx * 4];
            float bg[4] = {bg4.x, bg4.y, bg4.z, bg4.w};
            float bu[4] = {bu4.x, bu4.y, bu4.z, bu4.w};
#pragma unroll
            for (int i = 0; i < 4; i++)
#pragma unroll
                for (int j = 0; j < 4; j++) {
                    accg[i][j] += a[i] * bg[j];
                    accu[i][j] += a[i] * bu[j];
                }
        }
    }

#pragma unroll
    for (int i = 0; i < 4; i++) {
        int m = m0 + ty * 4 + i;
        if (m < cnt) {
            float wt = wts[ty * 4 + i];
            float4 hv;
            hv.x = silu_f(accg[i][0]) * accu[i][0] * wt;
            hv.y = silu_f(accg[i][1]) * accu[i][1] * wt;
            hv.z = silu_f(accg[i][2]) * accu[i][2] * wt;
            hv.w = silu_f(accg[i][3]) * accu[i][3] * wt;
            *(float4*)&g_h[(size_t)(base + m) * F_DIM + n0 + tx * 4] = hv;
        }
    }
}

__global__ __launch_bounds__(256) void ffn2_kernel(
    const float* __restrict__ wo, float* __restrict__ out)
{
    int e   = blockIdx.z;
    int cnt = g_cnt[e];
    int m0  = blockIdx.x * BM;
    if (m0 >= cnt) return;
    int n0   = blockIdx.y * BN;
    int base = g_base[e];

    __shared__ __align__(16) float As[BK][LDS_];
    __shared__ __align__(16) float Bs[BK][LDS_];
    __shared__ int toks[BM];

    int tid = threadIdx.x;
    if (tid < BM) {
        int m = m0 + tid;
        toks[tid] = (m < cnt) ? g_tok[base + m] : 0;
    }
    __syncthreads();

    const float* wo_ = wo + (size_t)e * D_DIM * F_DIM;

    int lm = tid >> 2;
    int lk = (tid & 3) * 4;
    int tx = tid & 15, ty = tid >> 4;

    float acc[4][4] = {{0.f}};

    bool valid = (m0 + lm) < cnt;
    const float* arow = g_h + (size_t)(base + m0 + lm) * F_DIM;
    const float* brow = wo_ + (size_t)(n0 + lm) * F_DIM;

    for (int k0 = 0; k0 < F_DIM; k0 += BK) {
        float4 av = valid ? *(const float4*)(arow + k0 + lk)
                          : make_float4(0.f, 0.f, 0.f, 0.f);
        float4 bv = *(const float4*)(brow + k0 + lk);
        __syncthreads();
        As[lk + 0][lm] = av.x; As[lk + 1][lm] = av.y;
        As[lk + 2][lm] = av.z; As[lk + 3][lm] = av.w;
        Bs[lk + 0][lm] = bv.x; Bs[lk + 1][lm] = bv.y;
        Bs[lk + 2][lm] = bv.z; Bs[lk + 3][lm] = bv.w;
        __syncthreads();
#pragma unroll
        for (int kk = 0; kk < BK; kk++) {
            float a[4];
            a[0] = As[kk][ty * 4 + 0]; a[1] = As[kk][ty * 4 + 1];
            a[2] = As[kk][ty * 4 + 2]; a[3] = As[kk][ty * 4 + 3];
            float4 b4 = *(const float4*)&Bs[kk][tx * 4];
            float b[4] = {b4.x, b4.y, b4.z, b4.w};
#pragma unroll
            for (int i = 0; i < 4; i++)
#pragma unroll
                for (int j = 0; j < 4; j++)
                    acc[i][j] += a[i] * b[j];
        }
    }

#pragma unroll
    for (int i = 0; i < 4; i++) {
        int mi = ty * 4 + i;
        int m = m0 + mi;
        if (m < cnt) {
            int tok = toks[mi];
            float* orow = out + (size_t)tok * D_DIM + n0 + tx * 4;
#pragma unroll
            for (int j = 0; j < 4; j++)
                atomicAdd(orow + j, acc[i][j]);
        }
    }
}

// ---------------------------------------------------------------------------
__global__ void aux_kernel(float* __restrict__ out, int out_size)
{
    if (threadIdx.x == 0) {
        float lb = 0.f;
        for (int e = 0; e < E_NUM; e++)
            lb += (g_f[e] / (float)(T_TOK * K_TOP)) * (g_P[e] / (float)T_TOK);
        float aux = 0.01f * (float)E_NUM * lb + 0.001f * (g_z / (float)T_TOK);
        if (out_size > T_TOK * D_DIM)
            out[T_TOK * D_DIM] = aux;
    }
}

// ---------------------------------------------------------------------------
extern "C" void kernel_launch(void* const* d_in, const int* in_sizes, int n_in,
                              void* d_out, int out_size)
{
    const float* x       = (const float*)d_in[0];
    const float* w_gate  = (const float*)d_in[1];
    const float* wi_gate = (const float*)d_in[2];
    const float* wi_up   = (const float*)d_in[3];
    const float* wo      = (const float*)d_in[4];
    float* out = (float*)d_out;

    cudaMemsetAsync(d_out, 0, (size_t)out_size * sizeof(float));
    init_kernel<<<1, 32>>>();
    router_kernel<<<T_TOK / 4, 128>>>(x, w_gate);
    scan_kernel<<<1, 512>>>();
    ffn1_kernel<<<dim3(CAP * 2 / BM, F_DIM / BN, E_NUM), 256>>>(x, wi_gate, wi_up);
    ffn2_kernel<<<dim3(CAP * 2 / BM, D_DIM / BN, E_NUM), 256>>>(wo, out);
    aux_kernel<<<1, 32>>>(out, out_size);
}

// round 3
// speedup vs baseline: 1.1754x; 1.1743x over previous
#include <cuda_runtime.h>
#include <cstdint>

// ---------------------------------------------------------------------------
// MoE forward: T=8192, D=768, F=3072, E=8, top-2, capacity=2560.
// Round 2: packed fp32x2 FMA (fma.rn.f32x2) GEMMs -> 2x fp32 throughput,
// exact fp32 numerics. Accumulators packed over M; A pairs come directly
// from LDS.128; B broadcast via mov.b64 dup.
// ---------------------------------------------------------------------------

#define T_TOK   8192
#define D_DIM   768
#define F_DIM   3072
#define E_NUM   8
#define K_TOP   2
#define CAP     2560
#define MAXROWS (T_TOK * K_TOP)

// ---- device scratch -------------------------------------------------------
__device__ int   g_topk_idx[T_TOK * 2];
__device__ float g_topk_w  [T_TOK * 2];
__device__ int   g_tok [MAXROWS];
__device__ float g_wt  [MAXROWS];
__device__ int   g_cnt [E_NUM];
__device__ int   g_base[E_NUM];
__device__ float g_P   [E_NUM];
__device__ float g_f   [E_NUM];
__device__ float g_z;
__device__ float g_h[(size_t)MAXROWS * F_DIM];   // ~201 MB hidden scratch

// ---- packed fp32x2 helpers ------------------------------------------------
typedef unsigned long long u64t;

__device__ __forceinline__ void fma2(u64t& acc, u64t a, u64t b) {
    asm("fma.rn.f32x2 %0, %1, %2, %0;" : "+l"(acc) : "l"(a), "l"(b));
}
__device__ __forceinline__ u64t dup2(float v) {
    u64t r;
    asm("mov.b64 %0, {%1, %1};" : "=l"(r) : "f"(v));
    return r;
}
__device__ __forceinline__ void unpack2(u64t v, float& lo, float& hi) {
    asm("mov.b64 {%0, %1}, %2;" : "=f"(lo), "=f"(hi) : "l"(v));
}

// ---------------------------------------------------------------------------
__global__ void init_kernel() {
    int t = threadIdx.x;
    if (t < E_NUM) { g_P[t] = 0.f; g_f[t] = 0.f; }
    if (t == 0) g_z = 0.f;
}

// ---------------------------------------------------------------------------
// Router: one warp per token.
// ---------------------------------------------------------------------------
__global__ __launch_bounds__(128) void router_kernel(
    const float* __restrict__ x, const float* __restrict__ w_gate)
{
    int warp = threadIdx.x >> 5;
    int lane = threadIdx.x & 31;
    int t = blockIdx.x * 4 + warp;
    if (t >= T_TOK) return;

    const float* xr = x + (size_t)t * D_DIM;
    float a[24];
#pragma unroll
    for (int i = 0; i < 24; i++) a[i] = xr[i * 32 + lane];

    float logits[E_NUM];
#pragma unroll
    for (int e = 0; e < E_NUM; e++) {
        const float* w = w_gate + (size_t)e * D_DIM;
        float s = 0.f;
#pragma unroll
        for (int i = 0; i < 24; i++) s += a[i] * w[i * 32 + lane];
#pragma unroll
        for (int o = 16; o; o >>= 1) s += __shfl_xor_sync(0xffffffffu, s, o);
        logits[e] = s;
    }

    if (lane == 0) {
        float mx = logits[0];
#pragma unroll
        for (int e = 1; e < E_NUM; e++) mx = fmaxf(mx, logits[e]);
        float pe[E_NUM], se = 0.f;
#pragma unroll
        for (int e = 0; e < E_NUM; e++) { pe[e] = expf(logits[e] - mx); se += pe[e]; }
        float inv = 1.f / se;

        int i0 = 0; float p0 = pe[0];
#pragma unroll
        for (int e = 1; e < E_NUM; e++) if (pe[e] > p0) { p0 = pe[e]; i0 = e; }
        int i1 = -1; float p1 = -1.f;
#pragma unroll
        for (int e = 0; e < E_NUM; e++) if (e != i0 && pe[e] > p1) { p1 = pe[e]; i1 = e; }

        float q0 = p0 * inv, q1 = p1 * inv;
        float sn = 1.f / (q0 + q1);
        g_topk_idx[t * 2 + 0] = i0;
        g_topk_idx[t * 2 + 1] = i1;
        g_topk_w  [t * 2 + 0] = q0 * sn;
        g_topk_w  [t * 2 + 1] = q1 * sn;

        float lse = mx + logf(se);
        atomicAdd(&g_z, lse * lse);
#pragma unroll
        for (int e = 0; e < E_NUM; e++) atomicAdd(&g_P[e], pe[e] * inv);
        atomicAdd(&g_f[i0], 1.f);
        atomicAdd(&g_f[i1], 1.f);
    }
}

// ---------------------------------------------------------------------------
// Scan/dispatch: 1 block, 16 warps; warp w handles (k = w>>3, e = w&7).
// ---------------------------------------------------------------------------
__global__ __launch_bounds__(512) void scan_kernel()
{
    __shared__ int tot[2][E_NUM];
    __shared__ int off1[E_NUM];
    __shared__ int baseS[E_NUM];

    int tid = threadIdx.x, w = tid >> 5, lane = tid & 31;
    int k = w >> 3, e = w & 7;

    int run = 0;
    for (int c = 0; c < T_TOK / 32; c++) {
        int t = c * 32 + lane;
        int f = (g_topk_idx[t * 2 + k] == e);
        run += __popc(__ballot_sync(0xffffffffu, f));
    }
    if (lane == 0) tot[k][e] = run;
    __syncthreads();

    if (tid == 0) {
        int b = 0;
        for (int ee = 0; ee < E_NUM; ee++) {
            int k0 = min(tot[0][ee], CAP);
            int k1 = min(tot[1][ee], CAP);
            off1[ee] = k0;
            int c = k0 + k1;
            g_cnt[ee] = c;
            baseS[ee] = b;
            g_base[ee] = b;
            b += c;
        }
    }
    __syncthreads();

    int pos0 = baseS[e] + (k == 0 ? 0 : off1[e]);
    run = 0;
    for (int c = 0; c < T_TOK / 32; c++) {
        int t = c * 32 + lane;
        bool f = (g_topk_idx[t * 2 + k] == e);
        unsigned bal = __ballot_sync(0xffffffffu, f);
        int rank = run + __popc(bal & ((1u << lane) - 1u));
        if (f && rank < CAP) {
            g_tok[pos0 + rank] = t;
            g_wt [pos0 + rank] = g_topk_w[t * 2 + k];
        }
        run += __popc(bal);
    }
}

// ---------------------------------------------------------------------------
// FFN1: [cnt x 3072] = silu(Xg @ Wg^T) * (Xg @ Wu^T) * wt
// Tile 128x64, BK=16, 256 threads, 8x4 microtile (packed pairs over M).
// ---------------------------------------------------------------------------
#define BK 16
#define LDA 132   // 128 + 4
#define LDB 68    // 64 + 4

__device__ __forceinline__ float silu_f(float g) {
    return g / (1.f + __expf(-g));
}

__global__ __launch_bounds__(256, 2) void ffn1_kernel(
    const float* __restrict__ x,
    const float* __restrict__ wig,
    const float* __restrict__ wiu)
{
    int e   = blockIdx.z;
    int cnt = g_cnt[e];
    int m0  = blockIdx.x * 128;
    if (m0 >= cnt) return;
    int n0   = blockIdx.y * 64;
    int base = g_base[e];

    __shared__ __align__(16) float As[BK][LDA];
    __shared__ __align__(16) float Bg[BK][LDB];
    __shared__ __align__(16) float Bu[BK][LDB];
    __shared__ int   toks[128];
    __shared__ float wts [128];

    int tid = threadIdx.x;
    if (tid < 128) {
        int m = m0 + tid;
        toks[tid] = (m < cnt) ? g_tok[base + m] : 0;
        wts [tid] = (m < cnt) ? g_wt [base + m] : 0.f;
    }
    __syncthreads();

    const float* wg_ = wig + (size_t)e * F_DIM * D_DIM;
    const float* wu_ = wiu + (size_t)e * F_DIM * D_DIM;

    int lr = tid >> 2;            // 0..63 (row, plus +64 for second half)
    int lq = (tid & 3) * 4;       // k-quad offset
    int tx = tid & 15, ty = tid >> 4;

    const float* a0 = x   + (size_t)toks[lr]      * D_DIM + lq;
    const float* a1 = x   + (size_t)toks[lr + 64] * D_DIM + lq;
    const float* gr = wg_ + (size_t)(n0 + lr) * D_DIM + lq;
    const float* ur = wu_ + (size_t)(n0 + lr) * D_DIM + lq;

    u64t accg[4][4], accu[4][4];
#pragma unroll
    for (int p = 0; p < 4; p++)
#pragma unroll
        for (int j = 0; j < 4; j++) { accg[p][j] = 0ull; accu[p][j] = 0ull; }

    for (int k0 = 0; k0 < D_DIM; k0 += BK) {
        float4 av0 = *(const float4*)(a0 + k0);
        float4 av1 = *(const float4*)(a1 + k0);
        float4 gv  = *(const float4*)(gr + k0);
        float4 uv  = *(const float4*)(ur + k0);
        __syncthreads();
        As[lq + 0][lr] = av0.x; As[lq + 1][lr] = av0.y;
        As[lq + 2][lr] = av0.z; As[lq + 3][lr] = av0.w;
        As[lq + 0][lr + 64] = av1.x; As[lq + 1][lr + 64] = av1.y;
        As[lq + 2][lr + 64] = av1.z; As[lq + 3][lr + 64] = av1.w;
        Bg[lq + 0][lr] = gv.x; Bg[lq + 1][lr] = gv.y;
        Bg[lq + 2][lr] = gv.z; Bg[lq + 3][lr] = gv.w;
        Bu[lq + 0][lr] = uv.x; Bu[lq + 1][lr] = uv.y;
        Bu[lq + 2][lr] = uv.z; Bu[lq + 3][lr] = uv.w;
        __syncthreads();
#pragma unroll
        for (int kk = 0; kk < BK; kk++) {
            ulonglong2 p0 = *(const ulonglong2*)&As[kk][ty * 8];
            ulonglong2 p1 = *(const ulonglong2*)&As[kk][ty * 8 + 4];
            u64t ap[4] = { p0.x, p0.y, p1.x, p1.y };
            float4 bg4 = *(const float4*)&Bg[kk][tx * 4];
            float4 bu4 = *(const float4*)&Bu[kk][tx * 4];
            u64t bgd[4] = { dup2(bg4.x), dup2(bg4.y), dup2(bg4.z), dup2(bg4.w) };
            u64t bud[4] = { dup2(bu4.x), dup2(bu4.y), dup2(bu4.z), dup2(bu4.w) };
#pragma unroll
            for (int p = 0; p < 4; p++)
#pragma unroll
                for (int j = 0; j < 4; j++) {
                    fma2(accg[p][j], ap[p], bgd[j]);
                    fma2(accu[p][j], ap[p], bud[j]);
                }
        }
    }

#pragma unroll
    for (int p = 0; p < 4; p++)
#pragma unroll
        for (int h = 0; h < 2; h++) {
            int mi = ty * 8 + 2 * p + h;
            int m  = m0 + mi;
            if (m < cnt) {
                float wt = wts[mi];
                float4 hv;
                float glo, ghi, ulo, uhi;
                unpack2(accg[p][0], glo, ghi); unpack2(accu[p][0], ulo, uhi);
                hv.x = silu_f(h ? ghi : glo) * (h ? uhi : ulo) * wt;
                unpack2(accg[p][1], glo, ghi); unpack2(accu[p][1], ulo, uhi);
                hv.y = silu_f(h ? ghi : glo) * (h ? uhi : ulo) * wt;
                unpack2(accg[p][2], glo, ghi); unpack2(accu[p][2], ulo, uhi);
                hv.z = silu_f(h ? ghi : glo) * (h ? uhi : ulo) * wt;
                unpack2(accg[p][3], glo, ghi); unpack2(accu[p][3], ulo, uhi);
                hv.w = silu_f(h ? ghi : glo) * (h ? uhi : ulo) * wt;
                *(float4*)&g_h[(size_t)(base + m) * F_DIM + n0 + tx * 4] = hv;
            }
        }
}

// ---------------------------------------------------------------------------
// FFN2: out[tok] += H @ Wo^T. Tile 128x128, BK=16, 256 threads, 8x8 microtile.
// ---------------------------------------------------------------------------
__global__ __launch_bounds__(256, 2) void ffn2_kernel(
    const float* __restrict__ wo, float* __restrict__ out)
{
    int e   = blockIdx.z;
    int cnt = g_cnt[e];
    int m0  = blockIdx.x * 128;
    if (m0 >= cnt) return;
    int n0   = blockIdx.y * 128;
    int base = g_base[e];

    __shared__ __align__(16) float As[BK][LDA];
    __shared__ __align__(16) float Bs[BK][LDA];
    __shared__ int toks[128];

    int tid = threadIdx.x;
    if (tid < 128) {
        int m = m0 + tid;
        toks[tid] = (m < cnt) ? g_tok[base + m] : 0;
    }
    __syncthreads();

    const float* wo_ = wo + (size_t)e * D_DIM * F_DIM;

    int lr = tid >> 2;
    int lq = (tid & 3) * 4;
    int tx = tid & 15, ty = tid >> 4;

    bool v0 = (m0 + lr)      < cnt;
    bool v1 = (m0 + lr + 64) < cnt;
    const float* a0 = g_h + (size_t)(base + m0 + lr)      * F_DIM + lq;
    const float* a1 = g_h + (size_t)(base + m0 + lr + 64) * F_DIM + lq;
    const float* b0 = wo_ + (size_t)(n0 + lr) * F_DIM + lq;
    const float* b1 = wo_ + (size_t)(n0 + lr + 64) * F_DIM + lq;

    u64t acc[4][8];
#pragma unroll
    for (int p = 0; p < 4; p++)
#pragma unroll
        for (int j = 0; j < 8; j++) acc[p][j] = 0ull;

    const float4 z4 = make_float4(0.f, 0.f, 0.f, 0.f);
    for (int k0 = 0; k0 < F_DIM; k0 += BK) {
        float4 av0 = v0 ? *(const float4*)(a0 + k0) : z4;
        float4 av1 = v1 ? *(const float4*)(a1 + k0) : z4;
        float4 bv0 = *(const float4*)(b0 + k0);
        float4 bv1 = *(const float4*)(b1 + k0);
        __syncthreads();
        As[lq + 0][lr] = av0.x; As[lq + 1][lr] = av0.y;
        As[lq + 2][lr] = av0.z; As[lq + 3][lr] = av0.w;
        As[lq + 0][lr + 64] = av1.x; As[lq + 1][lr + 64] = av1.y;
        As[lq + 2][lr + 64] = av1.z; As[lq + 3][lr + 64] = av1.w;
        Bs[lq + 0][lr] = bv0.x; Bs[lq + 1][lr] = bv0.y;
        Bs[lq + 2][lr] = bv0.z; Bs[lq + 3][lr] = bv0.w;
        Bs[lq + 0][lr + 64] = bv1.x; Bs[lq + 1][lr + 64] = bv1.y;
        Bs[lq + 2][lr + 64] = bv1.z; Bs[lq + 3][lr + 64] = bv1.w;
        __syncthreads();
#pragma unroll
        for (int kk = 0; kk < BK; kk++) {
            ulonglong2 p0 = *(const ulonglong2*)&As[kk][ty * 8];
            ulonglong2 p1 = *(const ulonglong2*)&As[kk][ty * 8 + 4];
            u64t ap[4] = { p0.x, p0.y, p1.x, p1.y };
            float4 c0 = *(const float4*)&Bs[kk][tx * 8];
            float4 c1 = *(const float4*)&Bs[kk][tx * 8 + 4];
            u64t bd[8] = { dup2(c0.x), dup2(c0.y), dup2(c0.z), dup2(c0.w),
                           dup2(c1.x), dup2(c1.y), dup2(c1.z), dup2(c1.w) };
#pragma unroll
            for (int p = 0; p < 4; p++)
#pragma unroll
                for (int j = 0; j < 8; j++)
                    fma2(acc[p][j], ap[p], bd[j]);
        }
    }

#pragma unroll
    for (int p = 0; p < 4; p++)
#pragma unroll
        for (int h = 0; h < 2; h++) {
            int mi = ty * 8 + 2 * p + h;
            int m  = m0 + mi;
            if (m < cnt) {
                int tok = toks[mi];
                float* orow = out + (size_t)tok * D_DIM + n0 + tx * 8;
#pragma unroll
                for (int j = 0; j < 8; j++) {
                    float lo, hi;
                    unpack2(acc[p][j], lo, hi);
                    atomicAdd(orow + j, h ? hi : lo);
                }
            }
        }
}

// ---------------------------------------------------------------------------
__global__ void aux_kernel(float* __restrict__ out, int out_size)
{
    if (threadIdx.x == 0) {
        float lb = 0.f;
        for (int e = 0; e < E_NUM; e++)
            lb += (g_f[e] / (float)(T_TOK * K_TOP)) * (g_P[e] / (float)T_TOK);
        float aux = 0.01f * (float)E_NUM * lb + 0.001f * (g_z / (float)T_TOK);
        if (out_size > T_TOK * D_DIM)
            out[T_TOK * D_DIM] = aux;
    }
}

// ---------------------------------------------------------------------------
extern "C" void kernel_launch(void* const* d_in, const int* in_sizes, int n_in,
                              void* d_out, int out_size)
{
    const float* x       = (const float*)d_in[0];
    const float* w_gate  = (const float*)d_in[1];
    const float* wi_gate = (const float*)d_in[2];
    const float* wi_up   = (const float*)d_in[3];
    const float* wo      = (const float*)d_in[4];
    float* out = (float*)d_out;

    cudaMemsetAsync(d_out, 0, (size_t)out_size * sizeof(float));
    init_kernel<<<1, 32>>>();
    router_kernel<<<T_TOK / 4, 128>>>(x, w_gate);
    scan_kernel<<<1, 512>>>();
    ffn1_kernel<<<dim3(CAP * 2 / 128, F_DIM / 64, E_NUM), 256>>>(x, wi_gate, wi_up);
    ffn2_kernel<<<dim3(CAP * 2 / 128, D_DIM / 128, E_NUM), 256>>>(wo, out);
    aux_kernel<<<1, 32>>>(out, out_size);
}

// round 5
// speedup vs baseline: 2.3778x; 2.0230x over previous
#include <cuda_runtime.h>
#include <cuda_bf16.h>
#include <cstdint>

// ---------------------------------------------------------------------------
// MoE forward, Round 4: mma.sync bf16 (HMMA, sm_80+ path — tcgen05 is not
// available because the harness PTX target is sm_103 without the 'a' suffix).
// Split precision: a*b ~= ah*bh + ah*bl + al*bh, fp32 accumulate.
// cp.async 2-stage pipelined GEMMs, warp-tile 64x32, CTA tile 128x128.
// ---------------------------------------------------------------------------

#define T_TOK   8192
#define D_DIM   768
#define F_DIM   3072
#define E_NUM   8
#define CAP     2560
#define MAXROWS 16384
#define MAXR_PAD 16512

// ---- device scratch -------------------------------------------------------
__device__ int   g_topk_idx[T_TOK * 2];
__device__ float g_topk_w  [T_TOK * 2];
__device__ int   g_tok [MAXROWS];
__device__ float g_wt  [MAXROWS];
__device__ int   g_cnt [E_NUM];
__device__ int   g_base[E_NUM];
__device__ int   g_total;
__device__ float g_P   [E_NUM];
__device__ float g_f   [E_NUM];
__device__ float g_z;

__device__ __nv_bfloat16 g_Ah [(size_t)MAXR_PAD * D_DIM];
__device__ __nv_bfloat16 g_Al [(size_t)MAXR_PAD * D_DIM];
__device__ __nv_bfloat16 g_Wgh[(size_t)E_NUM * F_DIM * D_DIM];
__device__ __nv_bfloat16 g_Wgl[(size_t)E_NUM * F_DIM * D_DIM];
__device__ __nv_bfloat16 g_Wuh[(size_t)E_NUM * F_DIM * D_DIM];
__device__ __nv_bfloat16 g_Wul[(size_t)E_NUM * F_DIM * D_DIM];
__device__ __nv_bfloat16 g_Woh[(size_t)E_NUM * D_DIM * F_DIM];
__device__ __nv_bfloat16 g_Wol[(size_t)E_NUM * D_DIM * F_DIM];
__device__ __nv_bfloat16 g_Hh [(size_t)MAXR_PAD * F_DIM];
__device__ __nv_bfloat16 g_Hl [(size_t)MAXR_PAD * F_DIM];

// ---- helpers --------------------------------------------------------------
__device__ __forceinline__ uint32_t smem_u32(const void* p) {
    uint32_t a;
    asm("{ .reg .u64 t; cvta.to.shared.u64 t, %1; cvt.u32.u64 %0, t; }"
        : "=r"(a) : "l"(p));
    return a;
}
__device__ __forceinline__ void split2(float v, __nv_bfloat16& h, __nv_bfloat16& l) {
    h = __float2bfloat16(v);
    l = __float2bfloat16(v - __bfloat162float(h));
}
__device__ __forceinline__ uint32_t pack2(__nv_bfloat16 a, __nv_bfloat16 b) {
    return (uint32_t)__bfloat16_as_ushort(a) | ((uint32_t)__bfloat16_as_ushort(b) << 16);
}
__device__ __forceinline__ float silu_f(float g) {
    return g / (1.f + __expf(-g));
}

#define CP16(d, s)  asm volatile("cp.async.cg.shared.global [%0], [%1], 16;" :: "r"(d), "l"(s))
#define CPCOMMIT()  asm volatile("cp.async.commit_group;" ::: "memory")
#define CPWAIT1()   asm volatile("cp.async.wait_group 1;" ::: "memory")
#define CPWAIT0()   asm volatile("cp.async.wait_group 0;" ::: "memory")

// mma.sync m16n8k16 row.col f32 += bf16*bf16
#define MMA(d, a, b)                                                            \
    asm volatile("mma.sync.aligned.m16n8k16.row.col.f32.bf16.bf16.f32 "        \
        "{%0,%1,%2,%3}, {%4,%5,%6,%7}, {%8,%9}, {%0,%1,%2,%3};"                \
        : "+f"((d)[0]), "+f"((d)[1]), "+f"((d)[2]), "+f"((d)[3])               \
        : "r"((a)[0]), "r"((a)[1]), "r"((a)[2]), "r"((a)[3]),                  \
          "r"((b)[0]), "r"((b)[1]))

#define STR  80                  // padded smem row stride bytes (32 bf16 + 8 pad)
#define MATB (128 * STR)         // 10240 bytes per 128x32 matrix
#define STG1 (6 * MATB)          // ffn1 stage bytes
#define STG2 (4 * MATB)          // ffn2 stage bytes

// cp.async stage loader: NMAT matrices, 128 rows x 32 bf16 each.
template <int NMAT>
__device__ __forceinline__ void stage_load(uint32_t s0, int tid,
    const __nv_bfloat16* const* ptrs, int k0, int rs)
{
#pragma unroll
    for (int mat = 0; mat < NMAT; mat++) {
        const __nv_bfloat16* p = ptrs[mat] + k0;
        uint32_t sm = s0 + mat * MATB;
#pragma unroll
        for (int it = 0; it < 2; it++) {
            int idx = tid + it * 256;
            int r = idx >> 2, j = idx & 3;
            CP16(sm + r * STR + j * 16, p + (size_t)r * rs + j * 8);
        }
    }
    CPCOMMIT();
}

// ---------------------------------------------------------------------------
__global__ void init_kernel() {
    int t = threadIdx.x;
    if (t < E_NUM) { g_P[t] = 0.f; g_f[t] = 0.f; }
    if (t == 0) g_z = 0.f;
}

// ---------------------------------------------------------------------------
__global__ __launch_bounds__(128) void router_kernel(
    const float* __restrict__ x, const float* __restrict__ w_gate)
{
    int warp = threadIdx.x >> 5, lane = threadIdx.x & 31;
    int t = blockIdx.x * 4 + warp;
    if (t >= T_TOK) return;

    const float* xr = x + (size_t)t * D_DIM;
    float a[24];
#pragma unroll
    for (int i = 0; i < 24; i++) a[i] = xr[i * 32 + lane];

    float logits[E_NUM];
#pragma unroll
    for (int e = 0; e < E_NUM; e++) {
        const float* w = w_gate + (size_t)e * D_DIM;
        float s = 0.f;
#pragma unroll
        for (int i = 0; i < 24; i++) s += a[i] * w[i * 32 + lane];
#pragma unroll
        for (int o = 16; o; o >>= 1) s += __shfl_xor_sync(0xffffffffu, s, o);
        logits[e] = s;
    }

    if (lane == 0) {
        float mx = logits[0];
#pragma unroll
        for (int e = 1; e < E_NUM; e++) mx = fmaxf(mx, logits[e]);
        float pe[E_NUM], se = 0.f;
#pragma unroll
        for (int e = 0; e < E_NUM; e++) { pe[e] = expf(logits[e] - mx); se += pe[e]; }
        float inv = 1.f / se;

        int i0 = 0; float p0 = pe[0];
#pragma unroll
        for (int e = 1; e < E_NUM; e++) if (pe[e] > p0) { p0 = pe[e]; i0 = e; }
        int i1 = -1; float p1 = -1.f;
#pragma unroll
        for (int e = 0; e < E_NUM; e++) if (e != i0 && pe[e] > p1) { p1 = pe[e]; i1 = e; }

        float q0 = p0 * inv, q1 = p1 * inv;
        float sn = 1.f / (q0 + q1);
        g_topk_idx[t * 2 + 0] = i0;
        g_topk_idx[t * 2 + 1] = i1;
        g_topk_w  [t * 2 + 0] = q0 * sn;
        g_topk_w  [t * 2 + 1] = q1 * sn;

        float lse = mx + logf(se);
        atomicAdd(&g_z, lse * lse);
#pragma unroll
        for (int e = 0; e < E_NUM; e++) atomicAdd(&g_P[e], pe[e] * inv);
        atomicAdd(&g_f[i0], 1.f);
        atomicAdd(&g_f[i1], 1.f);
    }
}

// ---------------------------------------------------------------------------
__global__ __launch_bounds__(512) void scan_kernel()
{
    __shared__ int tot[2][E_NUM];
    __shared__ int off1[E_NUM];
    __shared__ int baseS[E_NUM];

    int tid = threadIdx.x, w = tid >> 5, lane = tid & 31;
    int k = w >> 3, e = w & 7;

    int run = 0;
    for (int c = 0; c < T_TOK / 32; c++) {
        int t = c * 32 + lane;
        int f = (g_topk_idx[t * 2 + k] == e);
        run += __popc(__ballot_sync(0xffffffffu, f));
    }
    if (lane == 0) tot[k][e] = run;
    __syncthreads();

    if (tid == 0) {
        int b = 0;
        for (int ee = 0; ee < E_NUM; ee++) {
            int k0 = min(tot[0][ee], CAP);
            int k1 = min(tot[1][ee], CAP);
            off1[ee] = k0;
            int c = k0 + k1;
            g_cnt[ee] = c;
            baseS[ee] = b;
            g_base[ee] = b;
            b += c;
        }
        g_total = b;
    }
    __syncthreads();

    int pos0 = baseS[e] + (k == 0 ? 0 : off1[e]);
    run = 0;
    for (int c = 0; c < T_TOK / 32; c++) {
        int t = c * 32 + lane;
        bool f = (g_topk_idx[t * 2 + k] == e);
        unsigned bal = __ballot_sync(0xffffffffu, f);
        int rank = run + __popc(bal & ((1u << lane) - 1u));
        if (f && rank < CAP) {
            g_tok[pos0 + rank] = t;
            g_wt [pos0 + rank] = g_topk_w[t * 2 + k];
        }
        run += __popc(bal);
    }
}

// ---------------------------------------------------------------------------
__global__ __launch_bounds__(256) void split_w_kernel(const float* __restrict__ src,
                                                      int which, int n4)
{
    int i = blockIdx.x * blockDim.x + threadIdx.x;
    if (i >= n4) return;
    __nv_bfloat16 *hi, *lo;
    if      (which == 0) { hi = g_Wgh; lo = g_Wgl; }
    else if (which == 1) { hi = g_Wuh; lo = g_Wul; }
    else                 { hi = g_Woh; lo = g_Wol; }
    float4 v = ((const float4*)src)[i];
    __nv_bfloat16 h0, l0, h1, l1, h2, l2, h3, l3;
    split2(v.x, h0, l0); split2(v.y, h1, l1);
    split2(v.z, h2, l2); split2(v.w, h3, l3);
    *(uint2*)(hi + (size_t)i * 4) = make_uint2(pack2(h0, h1), pack2(h2, h3));
    *(uint2*)(lo + (size_t)i * 4) = make_uint2(pack2(l0, l1), pack2(l2, l3));
}

// ---------------------------------------------------------------------------
__global__ __launch_bounds__(256) void compact_kernel(const float* __restrict__ x)
{
    int i = blockIdx.x * blockDim.x + threadIdx.x;
    if (i >= MAXR_PAD * (D_DIM / 4)) return;
    int row = i / (D_DIM / 4), c4 = i % (D_DIM / 4);
    float4 v = make_float4(0.f, 0.f, 0.f, 0.f);
    if (row < g_total) {
        int tok = g_tok[row];
        v = ((const float4*)(x + (size_t)tok * D_DIM))[c4];
    }
    __nv_bfloat16 h0, l0, h1, l1, h2, l2, h3, l3;
    split2(v.x, h0, l0); split2(v.y, h1, l1);
    split2(v.z, h2, l2); split2(v.w, h3, l3);
    *(uint2*)(g_Ah + (size_t)row * D_DIM + c4 * 4) = make_uint2(pack2(h0, h1), pack2(h2, h3));
    *(uint2*)(g_Al + (size_t)row * D_DIM + c4 * 4) = make_uint2(pack2(l0, l1), pack2(l2, l3));
}

// ---------------------------------------------------------------------------
// FFN1: CTA 128 rows x 128 h-cols (gate+up), K=768. 8 warps (2m x 4n),
// warp tile 64x32 for BOTH gate and up.
// ---------------------------------------------------------------------------
__global__ __launch_bounds__(256) void ffn1_mma()
{
    extern __shared__ __align__(16) char dsm[];
    __shared__ float wts_sh[128];

    int e   = blockIdx.z;
    int cnt = g_cnt[e];
    int m0  = blockIdx.y * 128;
    if (m0 >= cnt) return;
    int n0   = blockIdx.x * 128;
    int base = g_base[e];

    int tid = threadIdx.x, lane = tid & 31, wid = tid >> 5;
    int gid = lane >> 2, tig = lane & 3;
    int wm = wid >> 2, wn = wid & 3;

    if (tid < 128) {
        int m = m0 + tid;
        wts_sh[tid] = (m < cnt) ? g_wt[base + m] : 0.f;
    }

    const __nv_bfloat16* ptrs[6] = {
        g_Ah  + (size_t)(base + m0) * D_DIM,
        g_Al  + (size_t)(base + m0) * D_DIM,
        g_Wgh + (size_t)(e * F_DIM + n0) * D_DIM,
        g_Wgl + (size_t)(e * F_DIM + n0) * D_DIM,
        g_Wuh + (size_t)(e * F_DIM + n0) * D_DIM,
        g_Wul + (size_t)(e * F_DIM + n0) * D_DIM
    };
    uint32_t sb = smem_u32(dsm);

    float accg[4][4][4], accu[4][4][4];
#pragma unroll
    for (int mt = 0; mt < 4; mt++)
#pragma unroll
        for (int nt = 0; nt < 4; nt++)
#pragma unroll
            for (int r = 0; r < 4; r++) { accg[mt][nt][r] = 0.f; accu[mt][nt][r] = 0.f; }

    stage_load<6>(sb, tid, ptrs, 0, D_DIM);

    const int NCH = D_DIM / 32;   // 24
    for (int ch = 0; ch < NCH; ch++) {
        if (ch + 1 < NCH) {
            stage_load<6>(sb + ((ch + 1) & 1) * STG1, tid, ptrs, (ch + 1) * 32, D_DIM);
            CPWAIT1();
        } else {
            CPWAIT0();
        }
        __syncthreads();
        const char* s0 = dsm + (ch & 1) * STG1;
#pragma unroll
        for (int ks = 0; ks < 2; ks++) {
            int cb = ks * 32 + tig * 4;
            uint32_t ah[4][4], al[4][4];
#pragma unroll
            for (int mt = 0; mt < 4; mt++) {
                int r = wm * 64 + mt * 16 + gid;
                const char* Ah = s0 + 0 * MATB + r * STR + cb;
                const char* Al = s0 + 1 * MATB + r * STR + cb;
                ah[mt][0] = *(const uint32_t*)(Ah);
                ah[mt][1] = *(const uint32_t*)(Ah + 8 * STR);
                ah[mt][2] = *(const uint32_t*)(Ah + 16);
                ah[mt][3] = *(const uint32_t*)(Ah + 8 * STR + 16);
                al[mt][0] = *(const uint32_t*)(Al);
                al[mt][1] = *(const uint32_t*)(Al + 8 * STR);
                al[mt][2] = *(const uint32_t*)(Al + 16);
                al[mt][3] = *(const uint32_t*)(Al + 8 * STR + 16);
            }
            uint32_t bgh[4][2], bgl[4][2], buh[4][2], bul[4][2];
#pragma unroll
            for (int nt = 0; nt < 4; nt++) {
                int n = wn * 32 + nt * 8 + gid;
                const char* Gh = s0 + 2 * MATB + n * STR + cb;
                const char* Gl = s0 + 3 * MATB + n * STR + cb;
                const char* Uh = s0 + 4 * MATB + n * STR + cb;
                const char* Ul = s0 + 5 * MATB + n * STR + cb;
                bgh[nt][0] = *(const uint32_t*)(Gh); bgh[nt][1] = *(const uint32_t*)(Gh + 16);
                bgl[nt][0] = *(const uint32_t*)(Gl); bgl[nt][1] = *(const uint32_t*)(Gl + 16);
                buh[nt][0] = *(const uint32_t*)(Uh); buh[nt][1] = *(const uint32_t*)(Uh + 16);
                bul[nt][0] = *(const uint32_t*)(Ul); bul[nt][1] = *(const uint32_t*)(Ul + 16);
            }
#pragma unroll
            for (int mt = 0; mt < 4; mt++)
#pragma unroll
                for (int nt = 0; nt < 4; nt++) {
                    MMA(accg[mt][nt], ah[mt], bgh[nt]);
                    MMA(accu[mt][nt], ah[mt], buh[nt]);
                }
#pragma unroll
            for (int mt = 0; mt < 4; mt++)
#pragma unroll
                for (int nt = 0; nt < 4; nt++) {
                    MMA(accg[mt][nt], ah[mt], bgl[nt]);
                    MMA(accu[mt][nt], ah[mt], bul[nt]);
                }
#pragma unroll
            for (int mt = 0; mt < 4; mt++)
#pragma unroll
                for (int nt = 0; nt < 4; nt++) {
                    MMA(accg[mt][nt], al[mt], bgh[nt]);
                    MMA(accu[mt][nt], al[mt], buh[nt]);
                }
        }
        __syncthreads();
    }

    // epilogue: h = silu(g)*u*wt -> split bf16 hi/lo
#pragma unroll
    for (int mt = 0; mt < 4; mt++)
#pragma unroll
        for (int nt = 0; nt < 4; nt++) {
            int c0 = wn * 32 + nt * 8 + tig * 2;
#pragma unroll
            for (int half = 0; half < 2; half++) {
                int r = wm * 64 + mt * 16 + gid + half * 8;
                if (m0 + r < cnt) {
                    float wt = wts_sh[r];
                    float gg0 = accg[mt][nt][half * 2 + 0];
                    float gg1 = accg[mt][nt][half * 2 + 1];
                    float uu0 = accu[mt][nt][half * 2 + 0];
                    float uu1 = accu[mt][nt][half * 2 + 1];
                    float h0 = silu_f(gg0) * uu0 * wt;
                    float h1 = silu_f(gg1) * uu1 * wt;
                    __nv_bfloat16 a0, b0, a1, b1;
                    split2(h0, a0, b0); split2(h1, a1, b1);
                    size_t off = (size_t)(base + m0 + r) * F_DIM + n0 + c0;
                    *(uint32_t*)(g_Hh + off) = pack2(a0, a1);
                    *(uint32_t*)(g_Hl + off) = pack2(b0, b1);
                }
            }
        }
}

// ---------------------------------------------------------------------------
// FFN2: CTA 128 rows x 128 out-cols, K=3072. Same layout, single output,
// atomicAdd scatter back to tokens.
// ---------------------------------------------------------------------------
__global__ __launch_bounds__(256) void ffn2_mma(float* __restrict__ out)
{
    extern __shared__ __align__(16) char dsm[];
    __shared__ int toks_sh[128];

    int e   = blockIdx.z;
    int cnt = g_cnt[e];
    int m0  = blockIdx.y * 128;
    if (m0 >= cnt) return;
    int n0   = blockIdx.x * 128;
    int base = g_base[e];

    int tid = threadIdx.x, lane = tid & 31, wid = tid >> 5;
    int gid = lane >> 2, tig = lane & 3;
    int wm = wid >> 2, wn = wid & 3;

    if (tid < 128) {
        int m = m0 + tid;
        toks_sh[tid] = (m < cnt) ? g_tok[base + m] : 0;
    }

    const __nv_bfloat16* ptrs[4] = {
        g_Hh  + (size_t)(base + m0) * F_DIM,
        g_Hl  + (size_t)(base + m0) * F_DIM,
        g_Woh + (size_t)(e * D_DIM + n0) * F_DIM,
        g_Wol + (size_t)(e * D_DIM + n0) * F_DIM
    };
    uint32_t sb = smem_u32(dsm);

    float acc[4][4][4];
#pragma unroll
    for (int mt = 0; mt < 4; mt++)
#pragma unroll
        for (int nt = 0; nt < 4; nt++)
#pragma unroll
            for (int r = 0; r < 4; r++) acc[mt][nt][r] = 0.f;

    stage_load<4>(sb, tid, ptrs, 0, F_DIM);

    const int NCH = F_DIM / 32;   // 96
    for (int ch = 0; ch < NCH; ch++) {
        if (ch + 1 < NCH) {
            stage_load<4>(sb + ((ch + 1) & 1) * STG2, tid, ptrs, (ch + 1) * 32, F_DIM);
            CPWAIT1();
        } else {
            CPWAIT0();
        }
        __syncthreads();
        const char* s0 = dsm + (ch & 1) * STG2;
#pragma unroll
        for (int ks = 0; ks < 2; ks++) {
            int cb = ks * 32 + tig * 4;
            uint32_t ah[4][4], al[4][4];
#pragma unroll
            for (int mt = 0; mt < 4; mt++) {
                int r = wm * 64 + mt * 16 + gid;
                const char* Ah = s0 + 0 * MATB + r * STR + cb;
                const char* Al = s0 + 1 * MATB + r * STR + cb;
                ah[mt][0] = *(const uint32_t*)(Ah);
                ah[mt][1] = *(const uint32_t*)(Ah + 8 * STR);
                ah[mt][2] = *(const uint32_t*)(Ah + 16);
                ah[mt][3] = *(const uint32_t*)(Ah + 8 * STR + 16);
                al[mt][0] = *(const uint32_t*)(Al);
                al[mt][1] = *(const uint32_t*)(Al + 8 * STR);
                al[mt][2] = *(const uint32_t*)(Al + 16);
                al[mt][3] = *(const uint32_t*)(Al + 8 * STR + 16);
            }
            uint32_t bh[4][2], bl[4][2];
#pragma unroll
            for (int nt = 0; nt < 4; nt++) {
                int n = wn * 32 + nt * 8 + gid;
                const char* Bh = s0 + 2 * MATB + n * STR + cb;
                const char* Bl = s0 + 3 * MATB + n * STR + cb;
                bh[nt][0] = *(const uint32_t*)(Bh); bh[nt][1] = *(const uint32_t*)(Bh + 16);
                bl[nt][0] = *(const uint32_t*)(Bl); bl[nt][1] = *(const uint32_t*)(Bl + 16);
            }
#pragma unroll
            for (int mt = 0; mt < 4; mt++)
#pragma unroll
                for (int nt = 0; nt < 4; nt++)
                    MMA(acc[mt][nt], ah[mt], bh[nt]);
#pragma unroll
            for (int mt = 0; mt < 4; mt++)
#pragma unroll
                for (int nt = 0; nt < 4; nt++)
                    MMA(acc[mt][nt], ah[mt], bl[nt]);
#pragma unroll
            for (int mt = 0; mt < 4; mt++)
#pragma unroll
                for (int nt = 0; nt < 4; nt++)
                    MMA(acc[mt][nt], al[mt], bh[nt]);
        }
        __syncthreads();
    }

    // epilogue: scatter-add to out[tok]
#pragma unroll
    for (int mt = 0; mt < 4; mt++)
#pragma unroll
        for (int nt = 0; nt < 4; nt++) {
            int c0 = wn * 32 + nt * 8 + tig * 2;
#pragma unroll
            for (int half = 0; half < 2; half++) {
                int r = wm * 64 + mt * 16 + gid + half * 8;
                if (m0 + r < cnt) {
                    int tok = toks_sh[r];
                    float* orow = out + (size_t)tok * D_DIM + n0 + c0;
                    atomicAdd(orow + 0, acc[mt][nt][half * 2 + 0]);
                    atomicAdd(orow + 1, acc[mt][nt][half * 2 + 1]);
                }
            }
        }
}

// ---------------------------------------------------------------------------
__global__ void aux_kernel(float* __restrict__ out, int out_size)
{
    if (threadIdx.x == 0) {
        float lb = 0.f;
        for (int e = 0; e < E_NUM; e++)
            lb += (g_f[e] / (float)(T_TOK * 2)) * (g_P[e] / (float)T_TOK);
        float aux = 0.01f * (float)E_NUM * lb + 0.001f * (g_z / (float)T_TOK);
        if (out_size > T_TOK * D_DIM)
            out[T_TOK * D_DIM] = aux;
    }
}

// ---------------------------------------------------------------------------
extern "C" void kernel_launch(void* const* d_in, const int* in_sizes, int n_in,
                              void* d_out, int out_size)
{
    const float* x       = (const float*)d_in[0];
    const float* w_gate  = (const float*)d_in[1];
    const float* wi_gate = (const float*)d_in[2];
    const float* wi_up   = (const float*)d_in[3];
    const float* wo      = (const float*)d_in[4];
    float* out = (float*)d_out;

    const int SMEM1 = 2 * STG1;   // 122880
    const int SMEM2 = 2 * STG2;   // 81920
    cudaFuncSetAttribute(ffn1_mma, cudaFuncAttributeMaxDynamicSharedMemorySize, SMEM1);
    cudaFuncSetAttribute(ffn2_mma, cudaFuncAttributeMaxDynamicSharedMemorySize, SMEM2);

    cudaMemsetAsync(d_out, 0, (size_t)out_size * sizeof(float));
    init_kernel<<<1, 32>>>();
    router_kernel<<<T_TOK / 4, 128>>>(x, w_gate);
    scan_kernel<<<1, 512>>>();

    int n4w = E_NUM * F_DIM * D_DIM / 4;
    split_w_kernel<<<(n4w + 255) / 256, 256>>>(wi_gate, 0, n4w);
    split_w_kernel<<<(n4w + 255) / 256, 256>>>(wi_up,   1, n4w);
    split_w_kernel<<<(n4w + 255) / 256, 256>>>(wo,      2, n4w);

    int nC = MAXR_PAD * (D_DIM / 4);
    compact_kernel<<<(nC + 255) / 256, 256>>>(x);

    ffn1_mma<<<dim3(F_DIM / 128, 2 * CAP / 128, E_NUM), 256, SMEM1>>>();
    ffn2_mma<<<dim3(D_DIM / 128, 2 * CAP / 128, E_NUM), 256, SMEM2>>>(out);
    aux_kernel<<<1, 32>>>(out, out_size);
}